// round 11
// baseline (speedup 1.0000x reference)
#include <cuda_runtime.h>
#include <math.h>
#include <stdint.h>

// Problem constants
#define BATCH 64
#define SEQ   512
#define HID   512
#define GATES 2048              // 4*HID
#define MROWS (SEQ*BATCH)       // 32768
#define HB    (BATCH*HID)       // one (dir) h plane
#define NBLK  128               // persistent grid size (64 per direction)

// ---------------------------------------------------------------------------
// Scratch (static __device__ globals; no runtime allocation)
// bf16 pair-permuted layout: a row of 512 k-values = 32 chunks of 16.
// Chunk = 8 uint32 words [p0,p4,p1,p5,p2,p6,p3,p7], p_i = pack(k=2i,k=2i+1).
// uint2 read at word 2*tq yields exactly the m16n8k16 fragment halves.
// ---------------------------------------------------------------------------
__device__ uint32_t g_xeb  [(size_t)SEQ*32*BATCH*8];   // [s][chunk][b][8]
__device__ uint32_t g_hsb_f[(size_t)SEQ*32*BATCH*8];   // [t][chunk][b][8]
__device__ uint32_t g_hsb_b[(size_t)SEQ*32*BATCH*8];
__device__ uint32_t g_hb   [2*2*32*BATCH*8];           // [buf][dir][chunk][b][8]
__device__ uint32_t g_wxb  [4][32][2048*8];            // [l*2+d][chunk][n*8+w]
__device__ float    g_xp_f [(size_t)SEQ*GATES*BATCH];  // [s][gk][b]
__device__ float    g_xp_b [(size_t)SEQ*GATES*BATCH];
__device__ float    g_h    [2*HB];                     // [dir][b][k] (final step)

// Barrier slots: ONE 128-byte L2 line per slot (stride 32 words) so the 64
// producer release-stores hit 64 distinct lines (no LTS same-line serialization).
#define SLOT_STRIDE 32
__device__ unsigned g_slot [2][64*SLOT_STRIDE];

// ---------------------------------------------------------------------------
// helpers
// ---------------------------------------------------------------------------
__device__ __forceinline__ uint32_t pk(float lo, float hi)
{
    uint32_t r;
    asm("cvt.rn.bf16x2.f32 %0, %1, %2;" : "=r"(r) : "f"(hi), "f"(lo));
    return r;
}

// D(16x8) += A(16x16) * B(16x8), bf16 inputs, fp32 accum.
__device__ __forceinline__ void mma16(float* c, const uint32_t* a, uint32_t b0, uint32_t b1)
{
    asm volatile(
        "mma.sync.aligned.m16n8k16.row.col.f32.bf16.bf16.f32 "
        "{%0,%1,%2,%3},{%4,%5,%6,%7},{%8,%9},{%0,%1,%2,%3};"
        : "+f"(c[0]), "+f"(c[1]), "+f"(c[2]), "+f"(c[3])
        : "r"(a[0]), "r"(a[1]), "r"(a[2]), "r"(a[3]), "r"(b0), "r"(b1));
}

__device__ __forceinline__ uint2 ldcg_u2(const uint32_t* p)
{
    uint2 v;
    asm volatile("ld.global.cg.v2.u32 {%0,%1}, [%2];"
                 : "=r"(v.x), "=r"(v.y) : "l"(p));
    return v;
}

__device__ __forceinline__ float tanh_ap(float x)
{
    float y;
    asm("tanh.approx.f32 %0, %1;" : "=f"(y) : "f"(x));
    return y;
}
__device__ __forceinline__ float sig_ap(float x)
{
    return fmaf(0.5f, tanh_ap(0.5f*x), 0.5f);
}

// ---------------------------------------------------------------------------
// Distributed per-direction grid barrier (64 blocks), padded slots.
// Arrive: one release-store to the block's own line (no contention).
// Wait: threads 0..63 each spin (acquire) on one line, then bar.sync.
// ---------------------------------------------------------------------------
__device__ __forceinline__ void bar_arrive(unsigned* slots, int kc, unsigned tgt)
{
    __syncthreads();   // all block stores precede thread-0's release store
    if (threadIdx.x == 0)
        asm volatile("st.release.gpu.global.u32 [%0], %1;"
                     :: "l"(slots + kc*SLOT_STRIDE), "r"(tgt) : "memory");
}

__device__ __forceinline__ void bar_wait(unsigned* slots, unsigned tgt)
{
    if (threadIdx.x < 64) {
        unsigned v;
        do {
            asm volatile("ld.acquire.gpu.global.u32 %0, [%1];"
                         : "=r"(v) : "l"(slots + threadIdx.x*SLOT_STRIDE) : "memory");
        } while ((int)(v - tgt) < 0);
    }
    __syncthreads();
}

// ---------------------------------------------------------------------------
// Embedding gather -> bf16 pair-permuted xe.
// ---------------------------------------------------------------------------
__global__ void embed_kernel(const int* __restrict__ x, const float* __restrict__ emb)
{
    int row = blockIdx.x*8 + (threadIdx.x >> 5);    // s*64 + b
    int c   = threadIdx.x & 31;                     // chunk
    int s = row >> 6, b = row & 63;
    int idx = x[b*SEQ + s];
    const float* src = emb + (size_t)idx*HID + c*16;
    float4 v0 = *(const float4*)src;
    float4 v1 = *(const float4*)(src + 4);
    float4 v2 = *(const float4*)(src + 8);
    float4 v3 = *(const float4*)(src + 12);
    uint32_t p0 = pk(v0.x,v0.y), p1 = pk(v0.z,v0.w);
    uint32_t p2 = pk(v1.x,v1.y), p3 = pk(v1.z,v1.w);
    uint32_t p4 = pk(v2.x,v2.y), p5 = pk(v2.z,v2.w);
    uint32_t p6 = pk(v3.x,v3.y), p7 = pk(v3.z,v3.w);
    uint4* dst = (uint4*)(g_xeb + ((size_t)(s*32 + c)*64 + b)*8);
    dst[0] = make_uint4(p0,p4,p1,p5);
    dst[1] = make_uint4(p2,p6,p3,p7);
}

// ---------------------------------------------------------------------------
// Pre-pack Wx (all 4 layer/dir tensors) into bf16 pair-permuted global.
// ---------------------------------------------------------------------------
__global__ void pack_w(const float* __restrict__ W0, const float* __restrict__ W1,
                       const float* __restrict__ W2, const float* __restrict__ W3)
{
    const float* Wt = (blockIdx.y == 0) ? W0 : (blockIdx.y == 1) ? W1
                    : (blockIdx.y == 2) ? W2 : W3;
    int n = blockIdx.x*8 + (threadIdx.x >> 5);
    int c = threadIdx.x & 31;
    const float* src = Wt + (size_t)n*HID + c*16;
    float4 v0 = *(const float4*)src;
    float4 v1 = *(const float4*)(src + 4);
    float4 v2 = *(const float4*)(src + 8);
    float4 v3 = *(const float4*)(src + 12);
    uint32_t p0 = pk(v0.x,v0.y), p1 = pk(v0.z,v0.w);
    uint32_t p2 = pk(v1.x,v1.y), p3 = pk(v1.z,v1.w);
    uint32_t p4 = pk(v2.x,v2.y), p5 = pk(v2.z,v2.w);
    uint32_t p6 = pk(v3.x,v3.y), p7 = pk(v3.z,v3.w);
    uint4* dst = (uint4*)(&g_wxb[blockIdx.y][c][n*8]);
    dst[0] = make_uint4(p0,p4,p1,p5);
    dst[1] = make_uint4(p2,p6,p3,p7);
}

// ---------------------------------------------------------------------------
// Input-projection GEMM (bf16 m16n8k16), smem-free, 64x64 WARP TILES.
// C_T[s][n][b] = sum_h A[s*64+b][h]*W[n][h] + bx[n] + bh[n]
// M=32768, N=2048, K=512. Block tile 128x128, 4 warps = 2(m) x 2(n),
// warp tile 64x64 (4 m-frags x 8 n-frags): fragment traffic 0.0625 B/MAC
// (1.5x less L1 than 32x64). A and B fragments loaded directly from
// pre-packed bf16 global (coalesced 256B per fragment).
// ---------------------------------------------------------------------------
__global__ void __launch_bounds__(128, 2)
gemm_xproj(int selA, int layer,
           const float* __restrict__ bxF, const float* __restrict__ bhF,
           const float* __restrict__ bxB, const float* __restrict__ bhB)
{
    int d = blockIdx.z;
    const uint32_t* A = (selA == 0) ? g_xeb : (d ? g_hsb_b : g_hsb_f);
    const uint32_t* B = &g_wxb[layer*2 + d][0][0];
    const float* bia = d ? bxB : bxF;
    const float* bib = d ? bhB : bhF;
    float* C = d ? g_xp_b : g_xp_f;

    int m0 = blockIdx.y * 128;
    int n0 = blockIdx.x * 128;
    int tid = threadIdx.x;
    int wid = tid >> 5, lane = tid & 31;
    int g = lane >> 2, tq = lane & 3;
    int wm = wid >> 1, wn = wid & 1;          // warp tile 64(m) x 64(n)

    float acc[4][8][4];
    #pragma unroll
    for (int mf = 0; mf < 4; mf++)
        #pragma unroll
        for (int nt = 0; nt < 8; nt++)
            #pragma unroll
            for (int q = 0; q < 4; q++) acc[mf][nt][q] = 0.f;

    // A fragment word offsets (chunk stride = 512 words)
    const uint32_t* Ap[4];
    #pragma unroll
    for (int mf = 0; mf < 4; mf++) {
        int m = m0 + wm*64 + mf*16 + g;
        Ap[mf] = A + ((size_t)(m >> 6))*32*512 + (size_t)(m & 63)*8 + 2*tq;
    }
    // B fragment base (chunk stride = 16384 words)
    const uint32_t* Bp = B + (size_t)(n0 + wn*64 + g)*8 + 2*tq;

    for (int it = 0; it < 16; it++) {
        #pragma unroll
        for (int c2 = 0; c2 < 2; c2++) {
            int ch = it*2 + c2;
            uint2 alo[4], ahi[4];
            #pragma unroll
            for (int mf = 0; mf < 4; mf++) {
                const uint32_t* pa = Ap[mf] + (size_t)ch*512;
                alo[mf] = *(const uint2*)pa;
                ahi[mf] = *(const uint2*)(pa + 64);   // rows +8
            }
            uint2 bb[8];
            #pragma unroll
            for (int nt = 0; nt < 8; nt++)
                bb[nt] = *(const uint2*)(Bp + (size_t)ch*16384 + nt*64);

            uint32_t a[4][4];
            #pragma unroll
            for (int mf = 0; mf < 4; mf++) {
                a[mf][0] = alo[mf].x; a[mf][1] = ahi[mf].x;
                a[mf][2] = alo[mf].y; a[mf][3] = ahi[mf].y;
            }
            #pragma unroll
            for (int nt = 0; nt < 8; nt++)
                #pragma unroll
                for (int mf = 0; mf < 4; mf++)
                    mma16(acc[mf][nt], a[mf], bb[nt].x, bb[nt].y);
        }
    }

    // epilogue: bias + store transposed C[s][n][b]
    #pragma unroll
    for (int mf = 0; mf < 4; mf++) {
        int m = m0 + wm*64 + mf*16 + g;
        int s1 = m >> 6,     b1 = m & 63;
        int s2 = (m+8) >> 6, b2 = (m+8) & 63;
        #pragma unroll
        for (int nt = 0; nt < 8; nt++) {
            int n = n0 + wn*64 + nt*8 + 2*tq;
            float bv0 = bia[n]   + bib[n];
            float bv1 = bia[n+1] + bib[n+1];
            C[((size_t)s1*GATES + n  )*64 + b1] = acc[mf][nt][0] + bv0;
            C[((size_t)s1*GATES + n+1)*64 + b1] = acc[mf][nt][1] + bv1;
            C[((size_t)s2*GATES + n  )*64 + b2] = acc[mf][nt][2] + bv0;
            C[((size_t)s2*GATES + n+1)*64 + b2] = acc[mf][nt][3] + bv1;
        }
    }
}

// ---------------------------------------------------------------------------
// Persistent LSTM layer (bf16 tensor cores), both directions, all 512 steps.
// 128 blocks: dir = blk>>6, kc = blk&63 -> 32 gate-rows (4 gates x 8 hid cols).
// 8 warps = 4 k-slices (128 k each) x 2 n-halves (32 b each). Weights in
// registers. h fragments ld.global.cg from the bf16 pair-permuted global h
// buffer. 4-way k-partial reduce via smem, fused pointwise (tanh.approx),
// padded-slot distributed barrier, xp(t+1) prefetched between arrive and wait.
// ---------------------------------------------------------------------------
#define SGP 68

__global__ void __launch_bounds__(256, 1)
lstm_layer(const float* __restrict__ WhF, const float* __restrict__ WhB,
           int rev_b, int store_hs)
{
    __shared__ float sG[4*32*SGP];         // [ks(4)][row(32)][SGP]

    const int dir = blockIdx.x >> 6;
    const int kc  = blockIdx.x & 63;
    const int tid = threadIdx.x;
    const int wid = tid >> 5, lane = tid & 31;
    const int g = lane >> 2, tq = lane & 3;
    const int ks = wid >> 1;               // k-slice 0..3 (128 k each)
    const int nh = wid & 1;                // n-half 0..1 (32 b each)

    unsigned* slots = g_slot[dir];
    const unsigned pbase = *(volatile unsigned*)(slots + kc*SLOT_STRIDE);
    unsigned tgt = pbase;

    const float* Wh  = dir ? WhB : WhF;
    const float* xpb = dir ? g_xp_b : g_xp_f;
    uint32_t*    hsb = dir ? g_hsb_b : g_hsb_f;

    // --- preload weights as bf16 A-fragments (once per layer) ---
    const float* wr[4];
    #pragma unroll
    for (int i = 0; i < 4; i++) {
        int lr = i*8 + g;                  // local rows g, g+8, g+16, g+24
        wr[i] = Wh + (size_t)((lr >> 3)*512 + kc*8 + (lr & 7)) * HID;
    }
    uint32_t aw[8][2][4];
    #pragma unroll
    for (int kt = 0; kt < 8; kt++) {
        int kb = ks*128 + kt*16 + 2*tq;
        #pragma unroll
        for (int mf = 0; mf < 2; mf++) {
            aw[kt][mf][0] = pk(wr[2*mf  ][kb],   wr[2*mf  ][kb+1]);
            aw[kt][mf][1] = pk(wr[2*mf+1][kb],   wr[2*mf+1][kb+1]);
            aw[kt][mf][2] = pk(wr[2*mf  ][kb+8], wr[2*mf  ][kb+9]);
            aw[kt][mf][3] = pk(wr[2*mf+1][kb+8], wr[2*mf+1][kb+9]);
        }
    }

    // --- clear owned slice of h buffer 0 ---
    {
        int b = tid >> 2, i = tid & 3;
        int pos = 2*i + (kc & 1);
        g_hb[(((0*2 + dir)*32 + (kc >> 1))*64 + b)*8 + pos] = 0;
    }

    // pointwise mapping (static across t -> c in registers)
    const int pb = tid >> 2;               // batch 0..63
    const int j0 = (tid & 3) * 2;          // hidden-col pair base 0,2,4,6
    float creg[2] = {0.f, 0.f};
    float xr[2][4];

    // initial barrier; prefetch xp(0) inside the wait slack
    tgt++;
    bar_arrive(slots, kc, tgt);
    {
        int xrow0 = (dir && rev_b) ? (SEQ-1) : 0;
        const float* xp0 = xpb + (size_t)xrow0 * (GATES*64);
        #pragma unroll
        for (int r = 0; r < 2; r++)
            #pragma unroll
            for (int gate = 0; gate < 4; gate++)
                xr[r][gate] = __ldcg(&xp0[((gate << 9) + kc*8 + j0 + r)*64 + pb]);
    }
    bar_wait(slots, tgt);

    for (int t = 0; t < SEQ; t++) {
        const uint32_t* hbin  = g_hb + (size_t)(((t  )&1)*2 + dir)*32*512;
        uint32_t*       hbout = g_hb + (size_t)(((t+1)&1)*2 + dir)*32*512;

        float acc[2][4][4];
        #pragma unroll
        for (int mf = 0; mf < 2; mf++)
            #pragma unroll
            for (int nt = 0; nt < 4; nt++)
                #pragma unroll
                for (int q = 0; q < 4; q++) acc[mf][nt][q] = 0.f;

        // --- MMA: h fragments straight from L2 (coalesced 256B per frag) ---
        #pragma unroll
        for (int kt = 0; kt < 8; kt++) {
            const uint32_t* base = hbin + (ks*8 + kt)*512;
            #pragma unroll
            for (int nt = 0; nt < 4; nt++) {
                uint2 bb = ldcg_u2(base + (nh*32 + nt*8 + g)*8 + 2*tq);
                mma16(acc[0][nt], aw[kt][0], bb.x, bb.y);
                mma16(acc[1][nt], aw[kt][1], bb.x, bb.y);
            }
        }

        // --- write k-partials ---
        #pragma unroll
        for (int mf = 0; mf < 2; mf++)
            #pragma unroll
            for (int nt = 0; nt < 4; nt++) {
                int b = nh*32 + nt*8 + 2*tq;
                *(float2*)&sG[(ks*32 + mf*16 + g    )*SGP + b] =
                    make_float2(acc[mf][nt][0], acc[mf][nt][1]);
                *(float2*)&sG[(ks*32 + mf*16 + g + 8)*SGP + b] =
                    make_float2(acc[mf][nt][2], acc[mf][nt][3]);
            }
        __syncthreads();

        // --- pointwise: thread owns cells (j0, pb), (j0+1, pb) ---
        float hv[2];
        #pragma unroll
        for (int r = 0; r < 2; r++) {
            int j = j0 + r;
            int kg = kc*8 + j;
            float v[4];
            #pragma unroll
            for (int gate = 0; gate < 4; gate++) {
                float s = xr[r][gate];
                #pragma unroll
                for (int k2 = 0; k2 < 4; k2++)
                    s += sG[(k2*32 + gate*8 + j)*SGP + pb];
                v[gate] = s;
            }
            float f  = sig_ap(v[0]);
            float ii = sig_ap(v[1]);
            float gg = tanh_ap(v[2]);
            float o  = sig_ap(v[3]);
            float c = f*creg[r] + ii*gg;
            creg[r] = c;
            hv[r] = o*tanh_ap(c);
            if (t == SEQ-1)
                g_h[dir*HB + pb*HID + kg] = hv[r];
        }
        // pack pair -> permuted bf16 global h (+ hs history for layer-1 GEMM)
        {
            uint32_t w = pk(hv[0], hv[1]);
            int pos = j0 + (kc & 1);
            hbout[((kc >> 1)*64 + pb)*8 + pos] = w;
            if (store_hs)
                hsb[((size_t)(t*32 + (kc >> 1))*64 + pb)*8 + pos] = w;
        }

        // --- barrier with xp(t+1) prefetch hidden in the wait slack ---
        tgt++;
        bar_arrive(slots, kc, tgt);
        if (t + 1 < SEQ) {
            int tn = t + 1;
            int xrow = (dir && rev_b) ? (SEQ-1-tn) : tn;
            const float* xpn = xpb + (size_t)xrow * (GATES*64);
            #pragma unroll
            for (int r = 0; r < 2; r++)
                #pragma unroll
                for (int gate = 0; gate < 4; gate++)
                    xr[r][gate] = __ldcg(&xpn[((gate << 9) + kc*8 + j0 + r)*64 + pb]);
        }
        bar_wait(slots, tgt);
    }
}

// ---------------------------------------------------------------------------
// Final FC + sigmoid. Final fp32 states in g_h[dir][b][k].
// ---------------------------------------------------------------------------
__global__ void final_fc(const float* __restrict__ fcw, const float* __restrict__ fcb,
                         float* __restrict__ out)
{
    int b = blockIdx.x;
    const float* hf = g_h + b*HID;
    const float* hb = g_h + HB + b*HID;
    float s = 0.f;
    for (int k = threadIdx.x; k < HID; k += 128)
        s += hf[k]*fcw[k] + hb[k]*fcw[HID + k];
    #pragma unroll
    for (int off = 16; off > 0; off >>= 1)
        s += __shfl_xor_sync(0xFFFFFFFFu, s, off);
    __shared__ float red[4];
    int warp = threadIdx.x >> 5, lane = threadIdx.x & 31;
    if (lane == 0) red[warp] = s;
    __syncthreads();
    if (threadIdx.x == 0) {
        float tot = red[0] + red[1] + red[2] + red[3] + fcb[0];
        out[b] = 1.f/(1.f + expf(-tot));
    }
}

// ---------------------------------------------------------------------------
// Launch sequence: 7 graph nodes.
// ---------------------------------------------------------------------------
extern "C" void kernel_launch(void* const* d_in, const int* in_sizes, int n_in,
                              void* d_out, int out_size)
{
    const int*   x    = (const int*)  d_in[0];
    const float* emb  = (const float*)d_in[1];
    const float* Wx_f = (const float*)d_in[2];
    const float* bx_f = (const float*)d_in[3];
    const float* Wh_f = (const float*)d_in[4];
    const float* bh_f = (const float*)d_in[5];
    const float* Wx_b = (const float*)d_in[6];
    const float* bx_b = (const float*)d_in[7];
    const float* Wh_b = (const float*)d_in[8];
    const float* bh_b = (const float*)d_in[9];
    const float* fcw  = (const float*)d_in[10];
    const float* fcb  = (const float*)d_in[11];
    float* out = (float*)d_out;

    const int WL = 4*HID*HID;
    const int BL = 4*HID;

    dim3 ggrid(GATES/128, MROWS/128, 2);   // (16, 256, 2)

    // 1. pre-pack Wx tensors to bf16 permuted global ([l*2+d] order)
    pack_w<<<dim3(GATES/8, 4), 256>>>(Wx_f, Wx_b, Wx_f + WL, Wx_b + WL);

    // 2. embedding -> packed bf16 xe
    embed_kernel<<<MROWS/8, 256>>>(x, emb);

    // 3. layer-0 input projections (A = xe), bias = bx + bh
    gemm_xproj<<<ggrid, 128>>>(0, 0, bx_f, bh_f, bx_b, bh_b);

    // 4. layer-0 recurrence (backward reads xp row 511-t, store hs)
    lstm_layer<<<NBLK, 256>>>(Wh_f, Wh_b, 1, 1);

    // 5. layer-1 input projections (A = packed bf16 hs per dir)
    gemm_xproj<<<ggrid, 128>>>(1, 1, bx_f + BL, bh_f + BL, bx_b + BL, bh_b + BL);

    // 6. layer-1 recurrence (both dirs read xp row t)
    lstm_layer<<<NBLK, 256>>>(Wh_f + WL, Wh_b + WL, 0, 0);

    // 7. final FC + sigmoid
    final_fc<<<BATCH, 128>>>(fcw, fcb, out);
}

// round 13
// speedup vs baseline: 1.0672x; 1.0672x over previous
#include <cuda_runtime.h>
#include <math.h>
#include <stdint.h>

// Problem constants
#define BATCH 64
#define SEQ   512
#define HID   512
#define GATES 2048              // 4*HID
#define MROWS (SEQ*BATCH)       // 32768
#define HB    (BATCH*HID)       // one (dir) h plane
#define NBLK  128               // persistent grid size (64 per direction)

// ---------------------------------------------------------------------------
// Scratch (static __device__ globals; no runtime allocation)
//
// CHUNK-PAIRED bf16 layout for GEMM operands (g_xeb / g_hsb_* / g_wxb):
// row m of 512 k = 16 chunk-PAIRS (32 k each). Group = 64 rows (m>>6).
//   word addr = ((m>>6)*16 + pc)*1024 + (m&63)*16 + off
// where within the 16-word cell, fragment words for chunk c=2pc live at
// off = 4*tq + {0,1} and for c=2pc+1 at off = 4*tq + {2,3}. One uint4 at
// off=4*tq yields BOTH chunks' m16n8k16 fragment halves -> ld.128.
// Producers write logical pairs p (k=2p,2p+1 within a 16-chunk) at
// off = (w>>1)*4 + (c&1)*2 + (w&1), w = 2*(p&3)+(p>>2).
//
// xp layout: [s][gate(4)][kpair(256)][b(64)][2] -> float2-addressable.
// The recurrence h ring g_hb keeps the round-10 permuted layout unchanged.
// ---------------------------------------------------------------------------
__device__ uint32_t g_xeb  [(size_t)MROWS*256];        // paired layout
__device__ uint32_t g_hsb_f[(size_t)MROWS*256];
__device__ uint32_t g_hsb_b[(size_t)MROWS*256];
__device__ uint32_t g_hb   [2*2*32*BATCH*8];           // [buf][dir][chunk][b][8]
__device__ uint32_t g_wxb  [4][(size_t)GATES*256];     // paired layout
__device__ float    g_xp_f [(size_t)SEQ*GATES*BATCH];  // [s][gate][kp][b][2]
__device__ float    g_xp_b [(size_t)SEQ*GATES*BATCH];
__device__ float    g_h    [2*HB];                     // [dir][b][k] (final step)

#define SLOT_STRIDE 32
__device__ unsigned g_slot [2][64*SLOT_STRIDE];

// ---------------------------------------------------------------------------
// helpers
// ---------------------------------------------------------------------------
__device__ __forceinline__ uint32_t pk(float lo, float hi)
{
    uint32_t r;
    asm("cvt.rn.bf16x2.f32 %0, %1, %2;" : "=r"(r) : "f"(hi), "f"(lo));
    return r;
}

// D(16x8) += A(16x16) * B(16x8), bf16 inputs, fp32 accum.
__device__ __forceinline__ void mma16(float* c, const uint32_t* a, uint32_t b0, uint32_t b1)
{
    asm volatile(
        "mma.sync.aligned.m16n8k16.row.col.f32.bf16.bf16.f32 "
        "{%0,%1,%2,%3},{%4,%5,%6,%7},{%8,%9},{%0,%1,%2,%3};"
        : "+f"(c[0]), "+f"(c[1]), "+f"(c[2]), "+f"(c[3])
        : "r"(a[0]), "r"(a[1]), "r"(a[2]), "r"(a[3]), "r"(b0), "r"(b1));
}

__device__ __forceinline__ uint2 ldcg_u2(const uint32_t* p)
{
    uint2 v;
    asm volatile("ld.global.cg.v2.u32 {%0,%1}, [%2];"
                 : "=r"(v.x), "=r"(v.y) : "l"(p));
    return v;
}

__device__ __forceinline__ float tanh_ap(float x)
{
    float y;
    asm("tanh.approx.f32 %0, %1;" : "=f"(y) : "f"(x));
    return y;
}
__device__ __forceinline__ float sig_ap(float x)
{
    return fmaf(0.5f, tanh_ap(0.5f*x), 0.5f);
}

// ---------------------------------------------------------------------------
// Distributed per-direction grid barrier (64 blocks), padded slots.
// ---------------------------------------------------------------------------
__device__ __forceinline__ void bar_arrive(unsigned* slots, int kc, unsigned tgt)
{
    __syncthreads();   // all block stores precede thread-0's release store
    if (threadIdx.x == 0)
        asm volatile("st.release.gpu.global.u32 [%0], %1;"
                     :: "l"(slots + kc*SLOT_STRIDE), "r"(tgt) : "memory");
}

__device__ __forceinline__ void bar_wait(unsigned* slots, unsigned tgt)
{
    if (threadIdx.x < 64) {
        unsigned v;
        do {
            asm volatile("ld.acquire.gpu.global.u32 %0, [%1];"
                         : "=r"(v) : "l"(slots + threadIdx.x*SLOT_STRIDE) : "memory");
        } while ((int)(v - tgt) < 0);
    }
    __syncthreads();
}

// ---------------------------------------------------------------------------
// Embedding gather -> chunk-paired bf16 xe.
// ---------------------------------------------------------------------------
__global__ void embed_kernel(const int* __restrict__ x, const float* __restrict__ emb)
{
    int row = blockIdx.x*8 + (threadIdx.x >> 5);    // s*64 + b
    int c   = threadIdx.x & 31;                     // 16-k chunk
    int s = row >> 6, b = row & 63;
    int idx = x[b*SEQ + s];
    const float* src = emb + (size_t)idx*HID + c*16;
    float4 v0 = *(const float4*)src;
    float4 v1 = *(const float4*)(src + 4);
    float4 v2 = *(const float4*)(src + 8);
    float4 v3 = *(const float4*)(src + 12);
    uint32_t p0 = pk(v0.x,v0.y), p1 = pk(v0.z,v0.w);
    uint32_t p2 = pk(v1.x,v1.y), p3 = pk(v1.z,v1.w);
    uint32_t p4 = pk(v2.x,v2.y), p5 = pk(v2.z,v2.w);
    uint32_t p6 = pk(v3.x,v3.y), p7 = pk(v3.z,v3.w);
    uint32_t* dst = g_xeb + (size_t)(s*16 + (c>>1))*1024 + b*16 + (c&1)*2;
    *(uint2*)(dst +  0) = make_uint2(p0, p4);
    *(uint2*)(dst +  4) = make_uint2(p1, p5);
    *(uint2*)(dst +  8) = make_uint2(p2, p6);
    *(uint2*)(dst + 12) = make_uint2(p3, p7);
}

// ---------------------------------------------------------------------------
// Pre-pack Wx (4 layer/dir tensors) -> chunk-paired bf16.
// ---------------------------------------------------------------------------
__global__ void pack_w(const float* __restrict__ W0, const float* __restrict__ W1,
                       const float* __restrict__ W2, const float* __restrict__ W3)
{
    const float* Wt = (blockIdx.y == 0) ? W0 : (blockIdx.y == 1) ? W1
                    : (blockIdx.y == 2) ? W2 : W3;
    int n = blockIdx.x*8 + (threadIdx.x >> 5);
    int c = threadIdx.x & 31;
    const float* src = Wt + (size_t)n*HID + c*16;
    float4 v0 = *(const float4*)src;
    float4 v1 = *(const float4*)(src + 4);
    float4 v2 = *(const float4*)(src + 8);
    float4 v3 = *(const float4*)(src + 12);
    uint32_t p0 = pk(v0.x,v0.y), p1 = pk(v0.z,v0.w);
    uint32_t p2 = pk(v1.x,v1.y), p3 = pk(v1.z,v1.w);
    uint32_t p4 = pk(v2.x,v2.y), p5 = pk(v2.z,v2.w);
    uint32_t p6 = pk(v3.x,v3.y), p7 = pk(v3.z,v3.w);
    uint32_t* dst = &g_wxb[blockIdx.y][(size_t)((n>>6)*16 + (c>>1))*1024 + (n&63)*16 + (c&1)*2];
    *(uint2*)(dst +  0) = make_uint2(p0, p4);
    *(uint2*)(dst +  4) = make_uint2(p1, p5);
    *(uint2*)(dst +  8) = make_uint2(p2, p6);
    *(uint2*)(dst + 12) = make_uint2(p3, p7);
}

// ---------------------------------------------------------------------------
// Input-projection GEMM (bf16 m16n8k16), smem-free, chunk-paired ld.128.
// C[s][gate][kp][b][2] = sum_h A[s*64+b][h]*W[n][h] + bx[n] + bh[n]
// M=32768, N=2048, K=512. BM=BN=128. 8 warps = 4(m) x 2(n), warp 32x64.
// Per chunk-pair (32 k): 12 ld.128 feed 32 MMAs (was 24 ld.64).
// ---------------------------------------------------------------------------
__global__ void __launch_bounds__(256, 2)
gemm_xproj(int selA, int layer,
           const float* __restrict__ bxF, const float* __restrict__ bhF,
           const float* __restrict__ bxB, const float* __restrict__ bhB)
{
    int d = blockIdx.z;
    const uint32_t* A = (selA == 0) ? g_xeb : (d ? g_hsb_b : g_hsb_f);
    const uint32_t* B = &g_wxb[layer*2 + d][0];
    const float* bia = d ? bxB : bxF;
    const float* bib = d ? bhB : bhF;
    float* C = d ? g_xp_b : g_xp_f;

    int m0 = blockIdx.y * 128;
    int n0 = blockIdx.x * 128;
    int tid = threadIdx.x;
    int wid = tid >> 5, lane = tid & 31;
    int g = lane >> 2, tq = lane & 3;
    int wm = wid >> 1, wn = wid & 1;          // warp tile 32(m) x 64(n)

    float acc[2][8][4];
    #pragma unroll
    for (int mf = 0; mf < 2; mf++)
        #pragma unroll
        for (int nt = 0; nt < 8; nt++)
            #pragma unroll
            for (int q = 0; q < 4; q++) acc[mf][nt][q] = 0.f;

    // A fragment bases (group stride 16384 words, pc stride 1024, row +8 -> +128)
    const uint32_t* Ap[2];
    #pragma unroll
    for (int mf = 0; mf < 2; mf++) {
        int m = m0 + wm*32 + mf*16 + g;
        Ap[mf] = A + (size_t)(m >> 6)*16384 + (size_t)(m & 63)*16 + 4*tq;
    }
    // B fragment base
    const uint32_t* Bp = B + (size_t)((n0 >> 6) + wn)*16384 + (size_t)g*16 + 4*tq;

    #pragma unroll 2
    for (int pc = 0; pc < 16; pc++) {
        uint4 va[2][2];                       // [mf][lo/hi rows]
        #pragma unroll
        for (int mf = 0; mf < 2; mf++) {
            const uint32_t* pa = Ap[mf] + pc*1024;
            va[mf][0] = *(const uint4*)pa;
            va[mf][1] = *(const uint4*)(pa + 128);   // rows +8
        }
        uint4 vb[8];
        #pragma unroll
        for (int nt = 0; nt < 8; nt++)
            vb[nt] = *(const uint4*)(Bp + pc*1024 + nt*128);

        uint32_t a0[2][4], a1[2][4];
        #pragma unroll
        for (int mf = 0; mf < 2; mf++) {
            a0[mf][0] = va[mf][0].x; a0[mf][1] = va[mf][1].x;
            a0[mf][2] = va[mf][0].y; a0[mf][3] = va[mf][1].y;
            a1[mf][0] = va[mf][0].z; a1[mf][1] = va[mf][1].z;
            a1[mf][2] = va[mf][0].w; a1[mf][3] = va[mf][1].w;
        }
        #pragma unroll
        for (int nt = 0; nt < 8; nt++) {
            mma16(acc[0][nt], a0[0], vb[nt].x, vb[nt].y);
            mma16(acc[1][nt], a0[1], vb[nt].x, vb[nt].y);
            mma16(acc[0][nt], a1[0], vb[nt].z, vb[nt].w);
            mma16(acc[1][nt], a1[1], vb[nt].z, vb[nt].w);
        }
    }

    // epilogue: bias + float2 store into xp [s][gate][kp][b][2]
    #pragma unroll
    for (int mf = 0; mf < 2; mf++) {
        int m = m0 + wm*32 + mf*16 + g;       // rows m, m+8 (same s-group)
        int s1 = m >> 6, b1 = m & 63;
        #pragma unroll
        for (int nt = 0; nt < 8; nt++) {
            int n = n0 + wn*64 + nt*8 + 2*tq; // even
            int gate = n >> 9;
            int kp = (n & 511) >> 1;
            float bv0 = bia[n]   + bib[n];
            float bv1 = bia[n+1] + bib[n+1];
            size_t base = ((size_t)(s1*4 + gate)*256 + kp)*128;
            *(float2*)&C[base + b1*2] =
                make_float2(acc[mf][nt][0] + bv0, acc[mf][nt][1] + bv1);
            *(float2*)&C[base + (b1+8)*2] =
                make_float2(acc[mf][nt][2] + bv0, acc[mf][nt][3] + bv1);
        }
    }
}

// ---------------------------------------------------------------------------
// Persistent LSTM layer — round-10 verbatim except: xp prefetch is float2
// from the new xp layout; hs store targets the chunk-paired g_hsb layout.
// ---------------------------------------------------------------------------
#define SGP 68

__global__ void __launch_bounds__(256, 1)
lstm_layer(const float* __restrict__ WhF, const float* __restrict__ WhB,
           int rev_b, int store_hs)
{
    __shared__ float sG[4*32*SGP];         // [ks(4)][row(32)][SGP]

    const int dir = blockIdx.x >> 6;
    const int kc  = blockIdx.x & 63;
    const int tid = threadIdx.x;
    const int wid = tid >> 5, lane = tid & 31;
    const int g = lane >> 2, tq = lane & 3;
    const int ks = wid >> 1;               // k-slice 0..3 (128 k each)
    const int nh = wid & 1;                // n-half 0..1 (32 b each)

    unsigned* slots = g_slot[dir];
    const unsigned pbase = *(volatile unsigned*)(slots + kc*SLOT_STRIDE);
    unsigned tgt = pbase;

    const float* Wh  = dir ? WhB : WhF;
    const float* xpb = dir ? g_xp_b : g_xp_f;
    uint32_t*    hsb = dir ? g_hsb_b : g_hsb_f;

    // --- preload weights as bf16 A-fragments (once per layer) ---
    const float* wr[4];
    #pragma unroll
    for (int i = 0; i < 4; i++) {
        int lr = i*8 + g;                  // local rows g, g+8, g+16, g+24
        wr[i] = Wh + (size_t)((lr >> 3)*512 + kc*8 + (lr & 7)) * HID;
    }
    uint32_t aw[8][2][4];
    #pragma unroll
    for (int kt = 0; kt < 8; kt++) {
        int kb = ks*128 + kt*16 + 2*tq;
        #pragma unroll
        for (int mf = 0; mf < 2; mf++) {
            aw[kt][mf][0] = pk(wr[2*mf  ][kb],   wr[2*mf  ][kb+1]);
            aw[kt][mf][1] = pk(wr[2*mf+1][kb],   wr[2*mf+1][kb+1]);
            aw[kt][mf][2] = pk(wr[2*mf  ][kb+8], wr[2*mf  ][kb+9]);
            aw[kt][mf][3] = pk(wr[2*mf+1][kb+8], wr[2*mf+1][kb+9]);
        }
    }

    // --- clear owned slice of h buffer 0 ---
    {
        int b = tid >> 2, i = tid & 3;
        int pos = 2*i + (kc & 1);
        g_hb[(((0*2 + dir)*32 + (kc >> 1))*64 + b)*8 + pos] = 0;
    }

    // pointwise mapping (static across t -> c in registers)
    const int pb = tid >> 2;               // batch 0..63
    const int j0 = (tid & 3) * 2;          // hidden-col pair base 0,2,4,6
    const int kp = kc*4 + (j0 >> 1);       // xp k-pair index
    // hs store word offset in the paired layout
    const int hsoff = (j0 >> 1)*4 + ((kc >> 1) & 1)*2 + (kc & 1);
    float creg[2] = {0.f, 0.f};
    float xr[2][4];

    // initial barrier; prefetch xp(0) inside the wait slack
    tgt++;
    bar_arrive(slots, kc, tgt);
    {
        int xrow0 = (dir && rev_b) ? (SEQ-1) : 0;
        const float* xp0 = xpb + (size_t)xrow0 * (GATES*64);
        #pragma unroll
        for (int gate = 0; gate < 4; gate++) {
            float2 v = *(const float2*)&xp0[((size_t)gate*256 + kp)*128 + pb*2];
            xr[0][gate] = v.x; xr[1][gate] = v.y;
        }
    }
    bar_wait(slots, tgt);

    for (int t = 0; t < SEQ; t++) {
        const uint32_t* hbin  = g_hb + (size_t)(((t  )&1)*2 + dir)*32*512;
        uint32_t*       hbout = g_hb + (size_t)(((t+1)&1)*2 + dir)*32*512;

        float acc[2][4][4];
        #pragma unroll
        for (int mf = 0; mf < 2; mf++)
            #pragma unroll
            for (int nt = 0; nt < 4; nt++)
                #pragma unroll
                for (int q = 0; q < 4; q++) acc[mf][nt][q] = 0.f;

        // --- MMA: h fragments straight from L2 (coalesced 256B per frag) ---
        #pragma unroll
        for (int kt = 0; kt < 8; kt++) {
            const uint32_t* base = hbin + (ks*8 + kt)*512;
            #pragma unroll
            for (int nt = 0; nt < 4; nt++) {
                uint2 bb = ldcg_u2(base + (nh*32 + nt*8 + g)*8 + 2*tq);
                mma16(acc[0][nt], aw[kt][0], bb.x, bb.y);
                mma16(acc[1][nt], aw[kt][1], bb.x, bb.y);
            }
        }

        // --- write k-partials ---
        #pragma unroll
        for (int mf = 0; mf < 2; mf++)
            #pragma unroll
            for (int nt = 0; nt < 4; nt++) {
                int b = nh*32 + nt*8 + 2*tq;
                *(float2*)&sG[(ks*32 + mf*16 + g    )*SGP + b] =
                    make_float2(acc[mf][nt][0], acc[mf][nt][1]);
                *(float2*)&sG[(ks*32 + mf*16 + g + 8)*SGP + b] =
                    make_float2(acc[mf][nt][2], acc[mf][nt][3]);
            }
        __syncthreads();

        // --- pointwise: thread owns cells (j0, pb), (j0+1, pb) ---
        float hv[2];
        #pragma unroll
        for (int r = 0; r < 2; r++) {
            int j = j0 + r;
            int kg = kc*8 + j;
            float v[4];
            #pragma unroll
            for (int gate = 0; gate < 4; gate++) {
                float s = xr[r][gate];
                #pragma unroll
                for (int k2 = 0; k2 < 4; k2++)
                    s += sG[(k2*32 + gate*8 + j)*SGP + pb];
                v[gate] = s;
            }
            float f  = sig_ap(v[0]);
            float ii = sig_ap(v[1]);
            float gg = tanh_ap(v[2]);
            float o  = sig_ap(v[3]);
            float c = f*creg[r] + ii*gg;
            creg[r] = c;
            hv[r] = o*tanh_ap(c);
            if (t == SEQ-1)
                g_h[dir*HB + pb*HID + kg] = hv[r];
        }
        // pack pair -> permuted bf16 global h (+ paired-layout hs history)
        {
            uint32_t w = pk(hv[0], hv[1]);
            int pos = j0 + (kc & 1);
            hbout[((kc >> 1)*64 + pb)*8 + pos] = w;
            if (store_hs)
                hsb[((size_t)t*16 + (kc >> 2))*1024 + pb*16 + hsoff] = w;
        }

        // --- barrier with xp(t+1) prefetch hidden in the wait slack ---
        tgt++;
        bar_arrive(slots, kc, tgt);
        if (t + 1 < SEQ) {
            int tn = t + 1;
            int xrow = (dir && rev_b) ? (SEQ-1-tn) : tn;
            const float* xpn = xpb + (size_t)xrow * (GATES*64);
            #pragma unroll
            for (int gate = 0; gate < 4; gate++) {
                float2 v = *(const float2*)&xpn[((size_t)gate*256 + kp)*128 + pb*2];
                xr[0][gate] = v.x; xr[1][gate] = v.y;
            }
        }
        bar_wait(slots, tgt);
    }
}

// ---------------------------------------------------------------------------
// Final FC + sigmoid. Final fp32 states in g_h[dir][b][k].
// ---------------------------------------------------------------------------
__global__ void final_fc(const float* __restrict__ fcw, const float* __restrict__ fcb,
                         float* __restrict__ out)
{
    int b = blockIdx.x;
    const float* hf = g_h + b*HID;
    const float* hb = g_h + HB + b*HID;
    float s = 0.f;
    for (int k = threadIdx.x; k < HID; k += 128)
        s += hf[k]*fcw[k] + hb[k]*fcw[HID + k];
    #pragma unroll
    for (int off = 16; off > 0; off >>= 1)
        s += __shfl_xor_sync(0xFFFFFFFFu, s, off);
    __shared__ float red[4];
    int warp = threadIdx.x >> 5, lane = threadIdx.x & 31;
    if (lane == 0) red[warp] = s;
    __syncthreads();
    if (threadIdx.x == 0) {
        float tot = red[0] + red[1] + red[2] + red[3] + fcb[0];
        out[b] = 1.f/(1.f + expf(-tot));
    }
}

// ---------------------------------------------------------------------------
// Launch sequence: 7 graph nodes.
// ---------------------------------------------------------------------------
extern "C" void kernel_launch(void* const* d_in, const int* in_sizes, int n_in,
                              void* d_out, int out_size)
{
    const int*   x    = (const int*)  d_in[0];
    const float* emb  = (const float*)d_in[1];
    const float* Wx_f = (const float*)d_in[2];
    const float* bx_f = (const float*)d_in[3];
    const float* Wh_f = (const float*)d_in[4];
    const float* bh_f = (const float*)d_in[5];
    const float* Wx_b = (const float*)d_in[6];
    const float* bx_b = (const float*)d_in[7];
    const float* Wh_b = (const float*)d_in[8];
    const float* bh_b = (const float*)d_in[9];
    const float* fcw  = (const float*)d_in[10];
    const float* fcb  = (const float*)d_in[11];
    float* out = (float*)d_out;

    const int WL = 4*HID*HID;
    const int BL = 4*HID;

    dim3 ggrid(GATES/128, MROWS/128, 2);   // (16, 256, 2)

    // 1. pre-pack Wx tensors -> chunk-paired bf16 ([l*2+d] order)
    pack_w<<<dim3(GATES/8, 4), 256>>>(Wx_f, Wx_b, Wx_f + WL, Wx_b + WL);

    // 2. embedding -> chunk-paired bf16 xe
    embed_kernel<<<MROWS/8, 256>>>(x, emb);

    // 3. layer-0 input projections (A = xe), bias = bx + bh
    gemm_xproj<<<ggrid, 256>>>(0, 0, bx_f, bh_f, bx_b, bh_b);

    // 4. layer-0 recurrence (backward reads xp row 511-t, store hs)
    lstm_layer<<<NBLK, 256>>>(Wh_f, Wh_b, 1, 1);

    // 5. layer-1 input projections (A = paired bf16 hs per dir)
    gemm_xproj<<<ggrid, 256>>>(1, 1, bx_f + BL, bh_f + BL, bx_b + BL, bh_b + BL);

    // 6. layer-1 recurrence (both dirs read xp row t)
    lstm_layer<<<NBLK, 256>>>(Wh_f + WL, Wh_b + WL, 0, 0);

    // 7. final FC + sigmoid
    final_fc<<<BATCH, 128>>>(fcw, fcb, out);
}

// round 14
// speedup vs baseline: 1.1770x; 1.1028x over previous
#include <cuda_runtime.h>
#include <math.h>
#include <stdint.h>

// Problem constants
#define BATCH 64
#define SEQ   512
#define HID   512
#define GATES 2048              // 4*HID
#define MROWS (SEQ*BATCH)       // 32768
#define HB    (BATCH*HID)       // one (dir) h plane
#define NBLK  128               // persistent grid size (64 per direction)

// ---------------------------------------------------------------------------
// Scratch (static __device__ globals; no runtime allocation)
// bf16 pair-permuted layout: a row of 512 k-values = 32 chunks of 16.
// Chunk = 8 uint32 words [p0,p4,p1,p5,p2,p6,p3,p7], p_i = pack(k=2i,k=2i+1).
// uint2 read at word 2*tq yields exactly the m16n8k16 fragment halves.
// ---------------------------------------------------------------------------
__device__ uint32_t g_xeb  [(size_t)SEQ*32*BATCH*8];   // [s][chunk][b][8]
__device__ uint32_t g_hsb_f[(size_t)SEQ*32*BATCH*8];   // [t][chunk][b][8]
__device__ uint32_t g_hsb_b[(size_t)SEQ*32*BATCH*8];
__device__ uint32_t g_hb   [2*2*32*BATCH*8];           // [buf][dir][chunk][b][8]
__device__ uint32_t g_wxb  [4][32][2048*8];            // [l*2+d][chunk][n*8+w]
__device__ float    g_xp_f [(size_t)SEQ*GATES*BATCH];  // [s][gk][b]
__device__ float    g_xp_b [(size_t)SEQ*GATES*BATCH];
__device__ float    g_h    [2*HB];                     // [dir][b][k] (final step)

// Per-producer progress flags: ONE 128-byte L2 line per flag (stride 32 words)
// so the 64 producer release-stores hit 64 distinct lines (no LTS same-line
// serialization) and waiter polls are distributed across LTS slices.
#define SLOT_STRIDE 32
__device__ unsigned g_flag [2][64*SLOT_STRIDE];

// ---------------------------------------------------------------------------
// helpers
// ---------------------------------------------------------------------------
__device__ __forceinline__ uint32_t pk(float lo, float hi)
{
    uint32_t r;
    asm("cvt.rn.bf16x2.f32 %0, %1, %2;" : "=r"(r) : "f"(hi), "f"(lo));
    return r;
}

// D(16x8) += A(16x16) * B(16x8), bf16 inputs, fp32 accum.
__device__ __forceinline__ void mma16(float* c, const uint32_t* a, uint32_t b0, uint32_t b1)
{
    asm volatile(
        "mma.sync.aligned.m16n8k16.row.col.f32.bf16.bf16.f32 "
        "{%0,%1,%2,%3},{%4,%5,%6,%7},{%8,%9},{%0,%1,%2,%3};"
        : "+f"(c[0]), "+f"(c[1]), "+f"(c[2]), "+f"(c[3])
        : "r"(a[0]), "r"(a[1]), "r"(a[2]), "r"(a[3]), "r"(b0), "r"(b1));
}

__device__ __forceinline__ uint2 ldcg_u2(const uint32_t* p)
{
    uint2 v;
    asm volatile("ld.global.cg.v2.u32 {%0,%1}, [%2];"
                 : "=r"(v.x), "=r"(v.y) : "l"(p));
    return v;
}

__device__ __forceinline__ float tanh_ap(float x)
{
    float y;
    asm("tanh.approx.f32 %0, %1;" : "=f"(y) : "f"(x));
    return y;
}
__device__ __forceinline__ float sig_ap(float x)
{
    return fmaf(0.5f, tanh_ap(0.5f*x), 0.5f);
}

// ---------------------------------------------------------------------------
// Embedding gather -> bf16 pair-permuted xe.
// ---------------------------------------------------------------------------
__global__ void embed_kernel(const int* __restrict__ x, const float* __restrict__ emb)
{
    int row = blockIdx.x*8 + (threadIdx.x >> 5);    // s*64 + b
    int c   = threadIdx.x & 31;                     // chunk
    int s = row >> 6, b = row & 63;
    int idx = x[b*SEQ + s];
    const float* src = emb + (size_t)idx*HID + c*16;
    float4 v0 = *(const float4*)src;
    float4 v1 = *(const float4*)(src + 4);
    float4 v2 = *(const float4*)(src + 8);
    float4 v3 = *(const float4*)(src + 12);
    uint32_t p0 = pk(v0.x,v0.y), p1 = pk(v0.z,v0.w);
    uint32_t p2 = pk(v1.x,v1.y), p3 = pk(v1.z,v1.w);
    uint32_t p4 = pk(v2.x,v2.y), p5 = pk(v2.z,v2.w);
    uint32_t p6 = pk(v3.x,v3.y), p7 = pk(v3.z,v3.w);
    uint4* dst = (uint4*)(g_xeb + ((size_t)(s*32 + c)*64 + b)*8);
    dst[0] = make_uint4(p0,p4,p1,p5);
    dst[1] = make_uint4(p2,p6,p3,p7);
}

// ---------------------------------------------------------------------------
// Pre-pack Wx (all 4 layer/dir tensors) into bf16 pair-permuted global.
// ---------------------------------------------------------------------------
__global__ void pack_w(const float* __restrict__ W0, const float* __restrict__ W1,
                       const float* __restrict__ W2, const float* __restrict__ W3)
{
    const float* Wt = (blockIdx.y == 0) ? W0 : (blockIdx.y == 1) ? W1
                    : (blockIdx.y == 2) ? W2 : W3;
    int n = blockIdx.x*8 + (threadIdx.x >> 5);
    int c = threadIdx.x & 31;
    const float* src = Wt + (size_t)n*HID + c*16;
    float4 v0 = *(const float4*)src;
    float4 v1 = *(const float4*)(src + 4);
    float4 v2 = *(const float4*)(src + 8);
    float4 v3 = *(const float4*)(src + 12);
    uint32_t p0 = pk(v0.x,v0.y), p1 = pk(v0.z,v0.w);
    uint32_t p2 = pk(v1.x,v1.y), p3 = pk(v1.z,v1.w);
    uint32_t p4 = pk(v2.x,v2.y), p5 = pk(v2.z,v2.w);
    uint32_t p6 = pk(v3.x,v3.y), p7 = pk(v3.z,v3.w);
    uint4* dst = (uint4*)(&g_wxb[blockIdx.y][c][n*8]);
    dst[0] = make_uint4(p0,p4,p1,p5);
    dst[1] = make_uint4(p2,p6,p3,p7);
}

// ---------------------------------------------------------------------------
// Input-projection GEMM (bf16 m16n8k16), smem-free: A and B fragments both
// loaded directly from pre-packed bf16 global (coalesced 256B per fragment).
// C_T[s][n][b] = sum_h A[s*64+b][h]*W[n][h] + bx[n] + bh[n]
// M=32768, N=2048, K=512. BM=BN=128. 8 warps = 4(m) x 2(n), warp 32x64.
// ---------------------------------------------------------------------------
__global__ void __launch_bounds__(256, 2)
gemm_xproj(int selA, int layer,
           const float* __restrict__ bxF, const float* __restrict__ bhF,
           const float* __restrict__ bxB, const float* __restrict__ bhB)
{
    int d = blockIdx.z;
    const uint32_t* A = (selA == 0) ? g_xeb : (d ? g_hsb_b : g_hsb_f);
    const uint32_t* B = &g_wxb[layer*2 + d][0][0];
    const float* bia = d ? bxB : bxF;
    const float* bib = d ? bhB : bhF;
    float* C = d ? g_xp_b : g_xp_f;

    int m0 = blockIdx.y * 128;
    int n0 = blockIdx.x * 128;
    int tid = threadIdx.x;
    int wid = tid >> 5, lane = tid & 31;
    int g = lane >> 2, tq = lane & 3;
    int wm = wid >> 1, wn = wid & 1;          // warp tile 32(m) x 64(n)

    float acc[2][8][4];
    #pragma unroll
    for (int mf = 0; mf < 2; mf++)
        #pragma unroll
        for (int nt = 0; nt < 8; nt++)
            #pragma unroll
            for (int q = 0; q < 4; q++) acc[mf][nt][q] = 0.f;

    // A fragment word offsets (chunk stride = 512 words)
    const uint32_t* Ap[2];
    #pragma unroll
    for (int mf = 0; mf < 2; mf++) {
        int m = m0 + wm*32 + mf*16 + g;
        Ap[mf] = A + ((size_t)(m >> 6))*32*512 + (size_t)(m & 63)*8 + 2*tq;
    }
    // B fragment base (chunk stride = 16384 words)
    const uint32_t* Bp = B + (size_t)(n0 + wn*64 + g)*8 + 2*tq;

    for (int it = 0; it < 16; it++) {
        #pragma unroll
        for (int c2 = 0; c2 < 2; c2++) {
            int ch = it*2 + c2;
            uint2 alo[2], ahi[2];
            #pragma unroll
            for (int mf = 0; mf < 2; mf++) {
                const uint32_t* pa = Ap[mf] + (size_t)ch*512;
                alo[mf] = *(const uint2*)pa;
                ahi[mf] = *(const uint2*)(pa + 64);   // rows +8
            }
            uint2 bb[8];
            #pragma unroll
            for (int nt = 0; nt < 8; nt++)
                bb[nt] = *(const uint2*)(Bp + (size_t)ch*16384 + nt*64);

            uint32_t a[2][4];
            #pragma unroll
            for (int mf = 0; mf < 2; mf++) {
                a[mf][0] = alo[mf].x; a[mf][1] = ahi[mf].x;
                a[mf][2] = alo[mf].y; a[mf][3] = ahi[mf].y;
            }
            #pragma unroll
            for (int nt = 0; nt < 8; nt++) {
                mma16(acc[0][nt], a[0], bb[nt].x, bb[nt].y);
                mma16(acc[1][nt], a[1], bb[nt].x, bb[nt].y);
            }
        }
    }

    // epilogue: bias + store transposed C[s][n][b]
    #pragma unroll
    for (int mf = 0; mf < 2; mf++) {
        int m = m0 + wm*32 + mf*16 + g;
        int s1 = m >> 6,     b1 = m & 63;
        int s2 = (m+8) >> 6, b2 = (m+8) & 63;
        #pragma unroll
        for (int nt = 0; nt < 8; nt++) {
            int n = n0 + wn*64 + nt*8 + 2*tq;
            float bv0 = bia[n]   + bib[n];
            float bv1 = bia[n+1] + bib[n+1];
            C[((size_t)s1*GATES + n  )*64 + b1] = acc[mf][nt][0] + bv0;
            C[((size_t)s1*GATES + n+1)*64 + b1] = acc[mf][nt][1] + bv1;
            C[((size_t)s2*GATES + n  )*64 + b2] = acc[mf][nt][2] + bv0;
            C[((size_t)s2*GATES + n+1)*64 + b2] = acc[mf][nt][3] + bv1;
        }
    }
}

// ---------------------------------------------------------------------------
// Persistent LSTM layer (bf16 tensor cores), both directions, all 512 steps.
// 128 blocks: dir = blk>>6, kc = blk&63 -> 32 gate-rows (4 gates x 8 hid cols).
// 8 warps = 4 k-slices (128 k each) x 2 n-halves (32 b each).
// Sync: PADDED per-producer flags (one L2 line each). Producer release-stores
// its own flag after its h-slice stores; each consumer warp acquire-polls only
// the 16 producers of its k-slice and proceeds as soon as they are ready
// (per-slice skew absorption; no global lockstep).
// Ring safety (depth-2 h ring): flag[Q] >= base+1+t implies Q finished its
// step-(t-1) reads (reads precede writes within an iteration), and every
// block observes ALL 64 flags (4 k-slices x 16) before its own h-write.
// ---------------------------------------------------------------------------
#define SGP 68

__global__ void __launch_bounds__(256, 1)
lstm_layer(const float* __restrict__ WhF, const float* __restrict__ WhB,
           int rev_b, int store_hs)
{
    __shared__ float sG[4*32*SGP];         // [ks(4)][row(32)][SGP]

    const int dir = blockIdx.x >> 6;
    const int kc  = blockIdx.x & 63;
    const int tid = threadIdx.x;
    const int wid = tid >> 5, lane = tid & 31;
    const int g = lane >> 2, tq = lane & 3;
    const int ks = wid >> 1;               // k-slice 0..3 (128 k each)
    const int nh = wid & 1;                // n-half 0..1 (32 b each)

    unsigned* flags = g_flag[dir];
    const unsigned pbase = *(volatile unsigned*)(flags + kc*SLOT_STRIDE);

    const float* Wh  = dir ? WhB : WhF;
    const float* xpb = dir ? g_xp_b : g_xp_f;
    uint32_t*    hsb = dir ? g_hsb_b : g_hsb_f;

    // --- preload weights as bf16 A-fragments (once per layer) ---
    const float* wr[4];
    #pragma unroll
    for (int i = 0; i < 4; i++) {
        int lr = i*8 + g;                  // local rows g, g+8, g+16, g+24
        wr[i] = Wh + (size_t)((lr >> 3)*512 + kc*8 + (lr & 7)) * HID;
    }
    uint32_t aw[8][2][4];
    #pragma unroll
    for (int kt = 0; kt < 8; kt++) {
        int kb = ks*128 + kt*16 + 2*tq;
        #pragma unroll
        for (int mf = 0; mf < 2; mf++) {
            aw[kt][mf][0] = pk(wr[2*mf  ][kb],   wr[2*mf  ][kb+1]);
            aw[kt][mf][1] = pk(wr[2*mf+1][kb],   wr[2*mf+1][kb+1]);
            aw[kt][mf][2] = pk(wr[2*mf  ][kb+8], wr[2*mf  ][kb+9]);
            aw[kt][mf][3] = pk(wr[2*mf+1][kb+8], wr[2*mf+1][kb+9]);
        }
    }

    // --- clear owned slice of h buffer 0, then publish readiness ---
    {
        int b = tid >> 2, i = tid & 3;
        int pos = 2*i + (kc & 1);
        g_hb[(((0*2 + dir)*32 + (kc >> 1))*64 + b)*8 + pos] = 0;
    }
    __syncthreads();
    if (tid == 0)
        asm volatile("st.release.gpu.global.u32 [%0], %1;"
                     :: "l"(flags + kc*SLOT_STRIDE), "r"(pbase + 1) : "memory");

    // pointwise mapping (static across t -> c in registers)
    const int pb = tid >> 2;               // batch 0..63
    const int j0 = (tid & 3) * 2;          // hidden-col pair base 0,2,4,6
    float creg[2] = {0.f, 0.f};

    // this warp's producer flag line (lanes 0..15 each watch one)
    const unsigned* myflag = flags + (ks*16 + (lane & 15))*SLOT_STRIDE;

    for (int t = 0; t < SEQ; t++) {
        const unsigned tgt = pbase + 1 + t;
        const uint32_t* hbin  = g_hb + (size_t)(((t  )&1)*2 + dir)*32*512;
        uint32_t*       hbout = g_hb + (size_t)(((t+1)&1)*2 + dir)*32*512;

        // xp(t) loads: no flag dependency, issue before polling (DRAM overlap)
        int xrow = (dir && rev_b) ? (SEQ-1-t) : t;
        const float* xp = xpb + (size_t)xrow * (GATES*64);
        float xr[2][4];
        #pragma unroll
        for (int r = 0; r < 2; r++)
            #pragma unroll
            for (int gate = 0; gate < 4; gate++)
                xr[r][gate] = __ldcg(&xp[((gate << 9) + kc*8 + j0 + r)*64 + pb]);

        // --- wait for this k-slice's 16 producers (padded lines, backoff) ---
        if (lane < 16) {
            unsigned v;
            int spins = 0;
            for (;;) {
                asm volatile("ld.acquire.gpu.global.u32 %0, [%1];"
                             : "=r"(v) : "l"(myflag) : "memory");
                if ((int)(v - tgt) >= 0) break;
                if (++spins > 2048) __nanosleep(64);
            }
        }
        __syncwarp();

        float acc[2][4][4];
        #pragma unroll
        for (int mf = 0; mf < 2; mf++)
            #pragma unroll
            for (int nt = 0; nt < 4; nt++)
                #pragma unroll
                for (int q = 0; q < 4; q++) acc[mf][nt][q] = 0.f;

        // --- MMA: h fragments straight from L2 (coalesced 256B per frag) ---
        #pragma unroll
        for (int kt = 0; kt < 8; kt++) {
            const uint32_t* base = hbin + (ks*8 + kt)*512;
            #pragma unroll
            for (int nt = 0; nt < 4; nt++) {
                uint2 bb = ldcg_u2(base + (nh*32 + nt*8 + g)*8 + 2*tq);
                mma16(acc[0][nt], aw[kt][0], bb.x, bb.y);
                mma16(acc[1][nt], aw[kt][1], bb.x, bb.y);
            }
        }

        // --- write k-partials ---
        #pragma unroll
        for (int mf = 0; mf < 2; mf++)
            #pragma unroll
            for (int nt = 0; nt < 4; nt++) {
                int b = nh*32 + nt*8 + 2*tq;
                *(float2*)&sG[(ks*32 + mf*16 + g    )*SGP + b] =
                    make_float2(acc[mf][nt][0], acc[mf][nt][1]);
                *(float2*)&sG[(ks*32 + mf*16 + g + 8)*SGP + b] =
                    make_float2(acc[mf][nt][2], acc[mf][nt][3]);
            }
        __syncthreads();

        // --- pointwise: thread owns cells (j0, pb), (j0+1, pb) ---
        float hv[2];
        #pragma unroll
        for (int r = 0; r < 2; r++) {
            int j = j0 + r;
            int kg = kc*8 + j;
            float v[4];
            #pragma unroll
            for (int gate = 0; gate < 4; gate++) {
                float s = xr[r][gate];
                #pragma unroll
                for (int k2 = 0; k2 < 4; k2++)
                    s += sG[(k2*32 + gate*8 + j)*SGP + pb];
                v[gate] = s;
            }
            float f  = sig_ap(v[0]);
            float ii = sig_ap(v[1]);
            float gg = tanh_ap(v[2]);
            float o  = sig_ap(v[3]);
            float c = f*creg[r] + ii*gg;
            creg[r] = c;
            hv[r] = o*tanh_ap(c);
            if (t == SEQ-1)
                g_h[dir*HB + pb*HID + kg] = hv[r];
        }
        // pack pair -> permuted bf16 global h (+ hs history for layer-1 GEMM)
        {
            uint32_t w = pk(hv[0], hv[1]);
            int pos = j0 + (kc & 1);
            hbout[((kc >> 1)*64 + pb)*8 + pos] = w;
            if (store_hs)
                hsb[((size_t)(t*32 + (kc >> 1))*64 + pb)*8 + pos] = w;
        }
        __syncthreads();   // all h-slice stores issued before the release flag
        if (tid == 0)
            asm volatile("st.release.gpu.global.u32 [%0], %1;"
                         :: "l"(flags + kc*SLOT_STRIDE), "r"(tgt + 1) : "memory");
    }
}

// ---------------------------------------------------------------------------
// Final FC + sigmoid. Final fp32 states in g_h[dir][b][k].
// ---------------------------------------------------------------------------
__global__ void final_fc(const float* __restrict__ fcw, const float* __restrict__ fcb,
                         float* __restrict__ out)
{
    int b = blockIdx.x;
    const float* hf = g_h + b*HID;
    const float* hb = g_h + HB + b*HID;
    float s = 0.f;
    for (int k = threadIdx.x; k < HID; k += 128)
        s += hf[k]*fcw[k] + hb[k]*fcw[HID + k];
    #pragma unroll
    for (int off = 16; off > 0; off >>= 1)
        s += __shfl_xor_sync(0xFFFFFFFFu, s, off);
    __shared__ float red[4];
    int warp = threadIdx.x >> 5, lane = threadIdx.x & 31;
    if (lane == 0) red[warp] = s;
    __syncthreads();
    if (threadIdx.x == 0) {
        float tot = red[0] + red[1] + red[2] + red[3] + fcb[0];
        out[b] = 1.f/(1.f + expf(-tot));
    }
}

// ---------------------------------------------------------------------------
// Launch sequence: 7 graph nodes.
// ---------------------------------------------------------------------------
extern "C" void kernel_launch(void* const* d_in, const int* in_sizes, int n_in,
                              void* d_out, int out_size)
{
    const int*   x    = (const int*)  d_in[0];
    const float* emb  = (const float*)d_in[1];
    const float* Wx_f = (const float*)d_in[2];
    const float* bx_f = (const float*)d_in[3];
    const float* Wh_f = (const float*)d_in[4];
    const float* bh_f = (const float*)d_in[5];
    const float* Wx_b = (const float*)d_in[6];
    const float* bx_b = (const float*)d_in[7];
    const float* Wh_b = (const float*)d_in[8];
    const float* bh_b = (const float*)d_in[9];
    const float* fcw  = (const float*)d_in[10];
    const float* fcb  = (const float*)d_in[11];
    float* out = (float*)d_out;

    const int WL = 4*HID*HID;
    const int BL = 4*HID;

    dim3 ggrid(GATES/128, MROWS/128, 2);   // (16, 256, 2)

    // 1. pre-pack Wx tensors to bf16 permuted global ([l*2+d] order)
    pack_w<<<dim3(GATES/8, 4), 256>>>(Wx_f, Wx_b, Wx_f + WL, Wx_b + WL);

    // 2. embedding -> packed bf16 xe
    embed_kernel<<<MROWS/8, 256>>>(x, emb);

    // 3. layer-0 input projections (A = xe), bias = bx + bh
    gemm_xproj<<<ggrid, 256>>>(0, 0, bx_f, bh_f, bx_b, bh_b);

    // 4. layer-0 recurrence (backward reads xp row 511-t, store hs)
    lstm_layer<<<NBLK, 256>>>(Wh_f, Wh_b, 1, 1);

    // 5. layer-1 input projections (A = packed bf16 hs per dir)
    gemm_xproj<<<ggrid, 256>>>(1, 1, bx_f + BL, bh_f + BL, bx_b + BL, bh_b + BL);

    // 6. layer-1 recurrence (both dirs read xp row t)
    lstm_layer<<<NBLK, 256>>>(Wh_f + WL, Wh_b + WL, 0, 0);

    // 7. final FC + sigmoid
    final_fc<<<BATCH, 128>>>(fcw, fcb, out);
}

// round 15
// speedup vs baseline: 1.1986x; 1.0184x over previous
#include <cuda_runtime.h>
#include <math.h>
#include <stdint.h>

// Problem constants
#define BATCH 64
#define SEQ   512
#define HID   512
#define GATES 2048              // 4*HID
#define MROWS (SEQ*BATCH)       // 32768
#define HB    (BATCH*HID)       // one (dir) h plane
#define NBLK  128               // persistent grid size (64 per direction)

// ---------------------------------------------------------------------------
// Scratch (static __device__ globals; no runtime allocation)
// bf16 pair-permuted layout: a row of 512 k-values = 32 chunks of 16.
// Chunk = 8 uint32 words [p0,p4,p1,p5,p2,p6,p3,p7], p_i = pack(k=2i,k=2i+1).
// uint2 read at word 2*tq yields exactly the m16n8k16 fragment halves.
// xp is bf16x2: word [s][n>>1][b] = pack(xp[n]+bias, xp[n+1]+bias), n even.
// ---------------------------------------------------------------------------
__device__ uint32_t g_xeb  [(size_t)SEQ*32*BATCH*8];   // [s][chunk][b][8]
__device__ uint32_t g_hsb_f[(size_t)SEQ*32*BATCH*8];   // [t][chunk][b][8]
__device__ uint32_t g_hsb_b[(size_t)SEQ*32*BATCH*8];
__device__ uint32_t g_hb   [2*2*32*BATCH*8];           // [buf][dir][chunk][b][8]
__device__ uint32_t g_wxb  [4][32][2048*8];            // [l*2+d][chunk][n*8+w]
__device__ uint32_t g_xp_f [(size_t)SEQ*1024*BATCH];   // bf16x2 [s][n2][b]
__device__ uint32_t g_xp_b [(size_t)SEQ*1024*BATCH];
__device__ float    g_h    [2*HB];                     // [dir][b][k] (final step)

// Per-producer progress flags: ONE 128-byte L2 line per flag (stride 32 words).
#define SLOT_STRIDE 32
__device__ unsigned g_flag [2][64*SLOT_STRIDE];

// ---------------------------------------------------------------------------
// helpers
// ---------------------------------------------------------------------------
__device__ __forceinline__ uint32_t pk(float lo, float hi)
{
    uint32_t r;
    asm("cvt.rn.bf16x2.f32 %0, %1, %2;" : "=r"(r) : "f"(hi), "f"(lo));
    return r;
}

// D(16x8) += A(16x16) * B(16x8), bf16 inputs, fp32 accum.
__device__ __forceinline__ void mma16(float* c, const uint32_t* a, uint32_t b0, uint32_t b1)
{
    asm volatile(
        "mma.sync.aligned.m16n8k16.row.col.f32.bf16.bf16.f32 "
        "{%0,%1,%2,%3},{%4,%5,%6,%7},{%8,%9},{%0,%1,%2,%3};"
        : "+f"(c[0]), "+f"(c[1]), "+f"(c[2]), "+f"(c[3])
        : "r"(a[0]), "r"(a[1]), "r"(a[2]), "r"(a[3]), "r"(b0), "r"(b1));
}

__device__ __forceinline__ uint2 ldcg_u2(const uint32_t* p)
{
    uint2 v;
    asm volatile("ld.global.cg.v2.u32 {%0,%1}, [%2];"
                 : "=r"(v.x), "=r"(v.y) : "l"(p));
    return v;
}

__device__ __forceinline__ uint32_t ldcg_u1(const uint32_t* p)
{
    uint32_t v;
    asm volatile("ld.global.cg.u32 %0, [%1];" : "=r"(v) : "l"(p));
    return v;
}

__device__ __forceinline__ float bf_lo(uint32_t w) { return __uint_as_float(w << 16); }
__device__ __forceinline__ float bf_hi(uint32_t w) { return __uint_as_float(w & 0xFFFF0000u); }

__device__ __forceinline__ float tanh_ap(float x)
{
    float y;
    asm("tanh.approx.f32 %0, %1;" : "=f"(y) : "f"(x));
    return y;
}
__device__ __forceinline__ float sig_ap(float x)
{
    return fmaf(0.5f, tanh_ap(0.5f*x), 0.5f);
}

// ---------------------------------------------------------------------------
// Embedding gather -> bf16 pair-permuted xe.
// ---------------------------------------------------------------------------
__global__ void embed_kernel(const int* __restrict__ x, const float* __restrict__ emb)
{
    int row = blockIdx.x*8 + (threadIdx.x >> 5);    // s*64 + b
    int c   = threadIdx.x & 31;                     // chunk
    int s = row >> 6, b = row & 63;
    int idx = x[b*SEQ + s];
    const float* src = emb + (size_t)idx*HID + c*16;
    float4 v0 = *(const float4*)src;
    float4 v1 = *(const float4*)(src + 4);
    float4 v2 = *(const float4*)(src + 8);
    float4 v3 = *(const float4*)(src + 12);
    uint32_t p0 = pk(v0.x,v0.y), p1 = pk(v0.z,v0.w);
    uint32_t p2 = pk(v1.x,v1.y), p3 = pk(v1.z,v1.w);
    uint32_t p4 = pk(v2.x,v2.y), p5 = pk(v2.z,v2.w);
    uint32_t p6 = pk(v3.x,v3.y), p7 = pk(v3.z,v3.w);
    uint4* dst = (uint4*)(g_xeb + ((size_t)(s*32 + c)*64 + b)*8);
    dst[0] = make_uint4(p0,p4,p1,p5);
    dst[1] = make_uint4(p2,p6,p3,p7);
}

// ---------------------------------------------------------------------------
// Pre-pack Wx (all 4 layer/dir tensors) into bf16 pair-permuted global.
// ---------------------------------------------------------------------------
__global__ void pack_w(const float* __restrict__ W0, const float* __restrict__ W1,
                       const float* __restrict__ W2, const float* __restrict__ W3)
{
    const float* Wt = (blockIdx.y == 0) ? W0 : (blockIdx.y == 1) ? W1
                    : (blockIdx.y == 2) ? W2 : W3;
    int n = blockIdx.x*8 + (threadIdx.x >> 5);
    int c = threadIdx.x & 31;
    const float* src = Wt + (size_t)n*HID + c*16;
    float4 v0 = *(const float4*)src;
    float4 v1 = *(const float4*)(src + 4);
    float4 v2 = *(const float4*)(src + 8);
    float4 v3 = *(const float4*)(src + 12);
    uint32_t p0 = pk(v0.x,v0.y), p1 = pk(v0.z,v0.w);
    uint32_t p2 = pk(v1.x,v1.y), p3 = pk(v1.z,v1.w);
    uint32_t p4 = pk(v2.x,v2.y), p5 = pk(v2.z,v2.w);
    uint32_t p6 = pk(v3.x,v3.y), p7 = pk(v3.z,v3.w);
    uint4* dst = (uint4*)(&g_wxb[blockIdx.y][c][n*8]);
    dst[0] = make_uint4(p0,p4,p1,p5);
    dst[1] = make_uint4(p2,p6,p3,p7);
}

// ---------------------------------------------------------------------------
// Input-projection GEMM (bf16 m16n8k16), smem-free: A and B fragments both
// loaded directly from pre-packed bf16 global (coalesced 256B per fragment).
// xp[s][n>>1][b] (bf16x2) = pack over n-pair of sum_h A*W + bx + bh.
// M=32768, N=2048, K=512. BM=BN=128. 8 warps = 4(m) x 2(n), warp 32x64.
// ---------------------------------------------------------------------------
__global__ void __launch_bounds__(256, 2)
gemm_xproj(int selA, int layer,
           const float* __restrict__ bxF, const float* __restrict__ bhF,
           const float* __restrict__ bxB, const float* __restrict__ bhB)
{
    int d = blockIdx.z;
    const uint32_t* A = (selA == 0) ? g_xeb : (d ? g_hsb_b : g_hsb_f);
    const uint32_t* B = &g_wxb[layer*2 + d][0][0];
    const float* bia = d ? bxB : bxF;
    const float* bib = d ? bhB : bhF;
    uint32_t* C = d ? g_xp_b : g_xp_f;

    int m0 = blockIdx.y * 128;
    int n0 = blockIdx.x * 128;
    int tid = threadIdx.x;
    int wid = tid >> 5, lane = tid & 31;
    int g = lane >> 2, tq = lane & 3;
    int wm = wid >> 1, wn = wid & 1;          // warp tile 32(m) x 64(n)

    float acc[2][8][4];
    #pragma unroll
    for (int mf = 0; mf < 2; mf++)
        #pragma unroll
        for (int nt = 0; nt < 8; nt++)
            #pragma unroll
            for (int q = 0; q < 4; q++) acc[mf][nt][q] = 0.f;

    // A fragment word offsets (chunk stride = 512 words)
    const uint32_t* Ap[2];
    #pragma unroll
    for (int mf = 0; mf < 2; mf++) {
        int m = m0 + wm*32 + mf*16 + g;
        Ap[mf] = A + ((size_t)(m >> 6))*32*512 + (size_t)(m & 63)*8 + 2*tq;
    }
    // B fragment base (chunk stride = 16384 words)
    const uint32_t* Bp = B + (size_t)(n0 + wn*64 + g)*8 + 2*tq;

    #pragma unroll 2
    for (int it = 0; it < 16; it++) {
        #pragma unroll
        for (int c2 = 0; c2 < 2; c2++) {
            int ch = it*2 + c2;
            uint2 alo[2], ahi[2];
            #pragma unroll
            for (int mf = 0; mf < 2; mf++) {
                const uint32_t* pa = Ap[mf] + (size_t)ch*512;
                alo[mf] = *(const uint2*)pa;
                ahi[mf] = *(const uint2*)(pa + 64);   // rows +8
            }
            uint2 bb[8];
            #pragma unroll
            for (int nt = 0; nt < 8; nt++)
                bb[nt] = *(const uint2*)(Bp + (size_t)ch*16384 + nt*64);

            uint32_t a[2][4];
            #pragma unroll
            for (int mf = 0; mf < 2; mf++) {
                a[mf][0] = alo[mf].x; a[mf][1] = ahi[mf].x;
                a[mf][2] = alo[mf].y; a[mf][3] = ahi[mf].y;
            }
            #pragma unroll
            for (int nt = 0; nt < 8; nt++) {
                mma16(acc[0][nt], a[0], bb[nt].x, bb[nt].y);
                mma16(acc[1][nt], a[1], bb[nt].x, bb[nt].y);
            }
        }
    }

    // epilogue: bias + packed bf16x2 store: C[s][n>>1][b]
    #pragma unroll
    for (int mf = 0; mf < 2; mf++) {
        int m = m0 + wm*32 + mf*16 + g;
        int s1 = m >> 6,     b1 = m & 63;
        int s2 = (m+8) >> 6, b2 = (m+8) & 63;
        #pragma unroll
        for (int nt = 0; nt < 8; nt++) {
            int n = n0 + wn*64 + nt*8 + 2*tq;        // even
            float bv0 = bia[n]   + bib[n];
            float bv1 = bia[n+1] + bib[n+1];
            C[((size_t)s1*1024 + (n >> 1))*64 + b1] =
                pk(acc[mf][nt][0] + bv0, acc[mf][nt][1] + bv1);
            C[((size_t)s2*1024 + (n >> 1))*64 + b2] =
                pk(acc[mf][nt][2] + bv0, acc[mf][nt][3] + bv1);
        }
    }
}

// ---------------------------------------------------------------------------
// Persistent LSTM layer (bf16 tensor cores), both directions, all 512 steps.
// 128 blocks: dir = blk>>6, kc = blk&63 -> 32 gate-rows (4 gates x 8 hid cols).
// 8 warps = 4 k-slices (128 k each) x 2 n-halves (32 b each).
// Sync: PADDED per-producer flags (one L2 line each); each consumer warp
// acquire-polls only the 16 producers of its k-slice (per-slice skew
// absorption). Ring safety: flag[Q] >= base+1+t implies Q finished its
// step-(t-1) reads, and every block observes ALL 64 flags before h-write.
// xp read as bf16x2: one word per gate covers the thread's (j0, j0+1) pair.
// ---------------------------------------------------------------------------
#define SGP 68

__global__ void __launch_bounds__(256, 1)
lstm_layer(const float* __restrict__ WhF, const float* __restrict__ WhB,
           int rev_b, int store_hs)
{
    __shared__ float sG[4*32*SGP];         // [ks(4)][row(32)][SGP]

    const int dir = blockIdx.x >> 6;
    const int kc  = blockIdx.x & 63;
    const int tid = threadIdx.x;
    const int wid = tid >> 5, lane = tid & 31;
    const int g = lane >> 2, tq = lane & 3;
    const int ks = wid >> 1;               // k-slice 0..3 (128 k each)
    const int nh = wid & 1;                // n-half 0..1 (32 b each)

    unsigned* flags = g_flag[dir];
    const unsigned pbase = *(volatile unsigned*)(flags + kc*SLOT_STRIDE);

    const float* Wh  = dir ? WhB : WhF;
    const uint32_t* xpb = dir ? g_xp_b : g_xp_f;
    uint32_t*    hsb = dir ? g_hsb_b : g_hsb_f;

    // --- preload weights as bf16 A-fragments (once per layer) ---
    const float* wr[4];
    #pragma unroll
    for (int i = 0; i < 4; i++) {
        int lr = i*8 + g;                  // local rows g, g+8, g+16, g+24
        wr[i] = Wh + (size_t)((lr >> 3)*512 + kc*8 + (lr & 7)) * HID;
    }
    uint32_t aw[8][2][4];
    #pragma unroll
    for (int kt = 0; kt < 8; kt++) {
        int kb = ks*128 + kt*16 + 2*tq;
        #pragma unroll
        for (int mf = 0; mf < 2; mf++) {
            aw[kt][mf][0] = pk(wr[2*mf  ][kb],   wr[2*mf  ][kb+1]);
            aw[kt][mf][1] = pk(wr[2*mf+1][kb],   wr[2*mf+1][kb+1]);
            aw[kt][mf][2] = pk(wr[2*mf  ][kb+8], wr[2*mf  ][kb+9]);
            aw[kt][mf][3] = pk(wr[2*mf+1][kb+8], wr[2*mf+1][kb+9]);
        }
    }

    // --- clear owned slice of h buffer 0, then publish readiness ---
    {
        int b = tid >> 2, i = tid & 3;
        int pos = 2*i + (kc & 1);
        g_hb[(((0*2 + dir)*32 + (kc >> 1))*64 + b)*8 + pos] = 0;
    }
    __syncthreads();
    if (tid == 0)
        asm volatile("st.release.gpu.global.u32 [%0], %1;"
                     :: "l"(flags + kc*SLOT_STRIDE), "r"(pbase + 1) : "memory");

    // pointwise mapping (static across t -> c in registers)
    const int pb = tid >> 2;               // batch 0..63
    const int j0 = (tid & 3) * 2;          // hidden-col pair base 0,2,4,6
    const int xw = kc*4 + (j0 >> 1);       // xp word index within a gate
    float creg[2] = {0.f, 0.f};

    // this warp's producer flag line (lanes 0..15 each watch one)
    const unsigned* myflag = flags + (ks*16 + (lane & 15))*SLOT_STRIDE;

    for (int t = 0; t < SEQ; t++) {
        const unsigned tgt = pbase + 1 + t;
        const uint32_t* hbin  = g_hb + (size_t)(((t  )&1)*2 + dir)*32*512;
        uint32_t*       hbout = g_hb + (size_t)(((t+1)&1)*2 + dir)*32*512;

        // xp(t) loads: no flag dependency, issue before polling (DRAM overlap)
        int xrow = (dir && rev_b) ? (SEQ-1-t) : t;
        const uint32_t* xp = xpb + (size_t)xrow * (1024*64);
        uint32_t xv[4];
        #pragma unroll
        for (int gate = 0; gate < 4; gate++)
            xv[gate] = ldcg_u1(&xp[((size_t)gate*256 + xw)*64 + pb]);

        // --- wait for this k-slice's 16 producers (padded lines, backoff) ---
        if (lane < 16) {
            unsigned v;
            int spins = 0;
            for (;;) {
                asm volatile("ld.acquire.gpu.global.u32 %0, [%1];"
                             : "=r"(v) : "l"(myflag) : "memory");
                if ((int)(v - tgt) >= 0) break;
                if (++spins > 2048) __nanosleep(64);
            }
        }
        __syncwarp();

        float acc[2][4][4];
        #pragma unroll
        for (int mf = 0; mf < 2; mf++)
            #pragma unroll
            for (int nt = 0; nt < 4; nt++)
                #pragma unroll
                for (int q = 0; q < 4; q++) acc[mf][nt][q] = 0.f;

        // --- MMA: h fragments straight from L2 (coalesced 256B per frag) ---
        #pragma unroll
        for (int kt = 0; kt < 8; kt++) {
            const uint32_t* base = hbin + (ks*8 + kt)*512;
            #pragma unroll
            for (int nt = 0; nt < 4; nt++) {
                uint2 bb = ldcg_u2(base + (nh*32 + nt*8 + g)*8 + 2*tq);
                mma16(acc[0][nt], aw[kt][0], bb.x, bb.y);
                mma16(acc[1][nt], aw[kt][1], bb.x, bb.y);
            }
        }

        // --- write k-partials ---
        #pragma unroll
        for (int mf = 0; mf < 2; mf++)
            #pragma unroll
            for (int nt = 0; nt < 4; nt++) {
                int b = nh*32 + nt*8 + 2*tq;
                *(float2*)&sG[(ks*32 + mf*16 + g    )*SGP + b] =
                    make_float2(acc[mf][nt][0], acc[mf][nt][1]);
                *(float2*)&sG[(ks*32 + mf*16 + g + 8)*SGP + b] =
                    make_float2(acc[mf][nt][2], acc[mf][nt][3]);
            }
        __syncthreads();

        // --- pointwise: thread owns cells (j0, pb), (j0+1, pb) ---
        float hv[2];
        #pragma unroll
        for (int r = 0; r < 2; r++) {
            int j = j0 + r;
            int kg = kc*8 + j;
            float v[4];
            #pragma unroll
            for (int gate = 0; gate < 4; gate++) {
                float s = r ? bf_hi(xv[gate]) : bf_lo(xv[gate]);
                #pragma unroll
                for (int k2 = 0; k2 < 4; k2++)
                    s += sG[(k2*32 + gate*8 + j)*SGP + pb];
                v[gate] = s;
            }
            float f  = sig_ap(v[0]);
            float ii = sig_ap(v[1]);
            float gg = tanh_ap(v[2]);
            float o  = sig_ap(v[3]);
            float c = f*creg[r] + ii*gg;
            creg[r] = c;
            hv[r] = o*tanh_ap(c);
            if (t == SEQ-1)
                g_h[dir*HB + pb*HID + kg] = hv[r];
        }
        // pack pair -> permuted bf16 global h (+ hs history for layer-1 GEMM)
        {
            uint32_t w = pk(hv[0], hv[1]);
            int pos = j0 + (kc & 1);
            hbout[((kc >> 1)*64 + pb)*8 + pos] = w;
            if (store_hs)
                hsb[((size_t)(t*32 + (kc >> 1))*64 + pb)*8 + pos] = w;
        }
        __syncthreads();   // all h-slice stores issued before the release flag
        if (tid == 0)
            asm volatile("st.release.gpu.global.u32 [%0], %1;"
                         :: "l"(flags + kc*SLOT_STRIDE), "r"(tgt + 1) : "memory");
    }
}

// ---------------------------------------------------------------------------
// Final FC + sigmoid. Final fp32 states in g_h[dir][b][k].
// ---------------------------------------------------------------------------
__global__ void final_fc(const float* __restrict__ fcw, const float* __restrict__ fcb,
                         float* __restrict__ out)
{
    int b = blockIdx.x;
    const float* hf = g_h + b*HID;
    const float* hb = g_h + HB + b*HID;
    float s = 0.f;
    for (int k = threadIdx.x; k < HID; k += 128)
        s += hf[k]*fcw[k] + hb[k]*fcw[HID + k];
    #pragma unroll
    for (int off = 16; off > 0; off >>= 1)
        s += __shfl_xor_sync(0xFFFFFFFFu, s, off);
    __shared__ float red[4];
    int warp = threadIdx.x >> 5, lane = threadIdx.x & 31;
    if (lane == 0) red[warp] = s;
    __syncthreads();
    if (threadIdx.x == 0) {
        float tot = red[0] + red[1] + red[2] + red[3] + fcb[0];
        out[b] = 1.f/(1.f + expf(-tot));
    }
}

// ---------------------------------------------------------------------------
// Launch sequence: 7 graph nodes.
// ---------------------------------------------------------------------------
extern "C" void kernel_launch(void* const* d_in, const int* in_sizes, int n_in,
                              void* d_out, int out_size)
{
    const int*   x    = (const int*)  d_in[0];
    const float* emb  = (const float*)d_in[1];
    const float* Wx_f = (const float*)d_in[2];
    const float* bx_f = (const float*)d_in[3];
    const float* Wh_f = (const float*)d_in[4];
    const float* bh_f = (const float*)d_in[5];
    const float* Wx_b = (const float*)d_in[6];
    const float* bx_b = (const float*)d_in[7];
    const float* Wh_b = (const float*)d_in[8];
    const float* bh_b = (const float*)d_in[9];
    const float* fcw  = (const float*)d_in[10];
    const float* fcb  = (const float*)d_in[11];
    float* out = (float*)d_out;

    const int WL = 4*HID*HID;
    const int BL = 4*HID;

    dim3 ggrid(GATES/128, MROWS/128, 2);   // (16, 256, 2)

    // 1. pre-pack Wx tensors to bf16 permuted global ([l*2+d] order)
    pack_w<<<dim3(GATES/8, 4), 256>>>(Wx_f, Wx_b, Wx_f + WL, Wx_b + WL);

    // 2. embedding -> packed bf16 xe
    embed_kernel<<<MROWS/8, 256>>>(x, emb);

    // 3. layer-0 input projections (A = xe), bias = bx + bh
    gemm_xproj<<<ggrid, 256>>>(0, 0, bx_f, bh_f, bx_b, bh_b);

    // 4. layer-0 recurrence (backward reads xp row 511-t, store hs)
    lstm_layer<<<NBLK, 256>>>(Wh_f, Wh_b, 1, 1);

    // 5. layer-1 input projections (A = packed bf16 hs per dir)
    gemm_xproj<<<ggrid, 256>>>(1, 1, bx_f + BL, bh_f + BL, bx_b + BL, bh_b + BL);

    // 6. layer-1 recurrence (both dirs read xp row t)
    lstm_layer<<<NBLK, 256>>>(Wh_f + WL, Wh_b + WL, 0, 0);

    // 7. final FC + sigmoid
    final_fc<<<BATCH, 128>>>(fcw, fcb, out);
}